// round 8
// baseline (speedup 1.0000x reference)
#include <cuda_runtime.h>
#include <cuda_bf16.h>
#include <stdint.h>

// Problem constants
#define NUM_QT   65
#define NUM_OT   151
#define PAIR_NUM 90
#define BATCH    8192
#define BOX      10
#define SLICE    (NUM_OT * NUM_OT)     // 22801 floats per (qt,p) slice
#define CAP      256                    // max batches per qt (mean 126, ~11 sigma headroom)
#define TILE     8192                   // floats per smem delta tile (32 KB)
// out elements = 65*90*151*151 = 133,385,850 = 5850 * 22801 exactly

// Scratch (device globals — no allocation allowed)
__device__ int                g_cnt[NUM_QT];
__device__ unsigned long long g_bucket[NUM_QT][PAIR_NUM][CAP];   // ~12 MB

__global__ void zero_cnt_kernel()
{
    int t = threadIdx.x;
    if (t < NUM_QT) g_cnt[t] = 0;
}

// One thread per batch: compute all 90 (cell, value) pairs, deposit into buckets.
__global__ void build_kernel(const int* __restrict__ obj_label,
                             const int* __restrict__ qus_type,
                             const float* __restrict__ attention)
{
    int b = blockIdx.x * blockDim.x + threadIdx.x;
    if (b >= BATCH) return;

    int qt = qus_type[b];
    int   lab[BOX];
    float att[BOX];
    #pragma unroll
    for (int k = 0; k < BOX; k++) {
        lab[k] = obj_label[b * BOX + k];
        att[k] = attention[b * BOX + k];
    }

    int pos = atomicAdd(&g_cnt[qt], 1);
    if (pos >= CAP) return;   // statistically impossible; guard anyway

    // Reference mapping: i = p/9, jj = p%9, j = jj + (jj>=i)
    //   ol1 = obj_label[b,j], ol2 = obj_label[b,i], a = att[b,j]*att[b,i]
    #pragma unroll
    for (int i = 0; i < BOX; i++) {
        #pragma unroll
        for (int jj = 0; jj < BOX - 1; jj++) {
            int j = jj + (jj >= i ? 1 : 0);
            int p = i * (BOX - 1) + jj;
            unsigned int cell = (unsigned int)(lab[j] * NUM_OT + lab[i]);
            float        v    = att[j] * att[i];
            g_bucket[qt][p][pos] =
                ((unsigned long long)cell << 32) | (unsigned long long)__float_as_uint(v);
        }
    }
}

// One block per (qt,p) slice. Tile the slice through a 32 KB smem delta buffer:
// zero tile -> scatter in-range entries (smem atomics) -> streaming copy+add.
// No global atomics; all global stores streaming (__stcs).
__global__ __launch_bounds__(256)
void fused_copy_scatter_kernel(const float* __restrict__ src,
                               float* __restrict__ out)
{
    __shared__ float tile[TILE];          // 32 KB
    __shared__ int   s_cell[CAP];
    __shared__ float s_val[CAP];

    const int s   = blockIdx.x;           // slice = qt*90 + p
    const int qt  = s / PAIR_NUM;
    const int p   = s - qt * PAIR_NUM;
    const int tid = threadIdx.x;

    int n = g_cnt[qt];
    if (n > CAP) n = CAP;
    for (int e = tid; e < n; e += 256) {
        unsigned long long pk = g_bucket[qt][p][e];
        s_cell[e] = (int)(pk >> 32);
        s_val[e]  = __uint_as_float((unsigned int)pk);
    }
    // (first __syncthreads below orders these writes before any read)

    const long long base = (long long)s * SLICE;
    const float* __restrict__ sp = src + base;
    float* __restrict__       dp = out + base;
    // 16B-aligned element indices are idx ≡ off (mod 4)
    const int off = (int)((4 - (base & 3)) & 3);

    for (int t0 = 0; t0 < SLICE; t0 += TILE) {
        const int t1  = (t0 + TILE < SLICE) ? (t0 + TILE) : SLICE;
        const int len = t1 - t0;

        // Phase 1: zero delta tile
        #pragma unroll 4
        for (int c = tid; c < len; c += 256) tile[c] = 0.0f;
        __syncthreads();

        // Phase 2: scatter entries hitting this tile (smem atomics, ~126 total/slice)
        for (int e = tid; e < n; e += 256) {
            int c = s_cell[e];
            if (c >= t0 && c < t1) atomicAdd(&tile[c - t0], s_val[e]);
        }
        __syncthreads();

        // Phase 3: streaming copy + add
        int h0 = t0 + ((off - t0) & 3);           // first 16B-aligned idx in tile
        if (h0 > t1) h0 = t1;
        {
            int idx = t0 + tid;                   // scalar head (<= 3 elems)
            if (idx < h0) __stcs(&dp[idx], __ldcs(&sp[idx]) + tile[idx - t0]);
        }
        const int nf4 = (t1 - h0) >> 2;
        const float4* __restrict__ sp4 = (const float4*)(sp + h0);
        float4* __restrict__       dp4 = (float4*)(dp + h0);
        const int mbase = h0 - t0;
        #pragma unroll 2
        for (int c = tid; c < nf4; c += 256) {
            float4 v = __ldcs(&sp4[c]);
            int m = mbase + (c << 2);
            v.x += tile[m];
            v.y += tile[m + 1];
            v.z += tile[m + 2];
            v.w += tile[m + 3];
            __stcs(&dp4[c], v);
        }
        const int done = h0 + (nf4 << 2);
        {
            int idx = done + tid;                 // scalar tail (<= 3 elems)
            if (idx < t1) __stcs(&dp[idx], __ldcs(&sp[idx]) + tile[idx - t0]);
        }
        __syncthreads();                          // protect tile before next zero
    }
}

extern "C" void kernel_launch(void* const* d_in, const int* in_sizes, int n_in,
                              void* d_out, int out_size)
{
    // metadata order: obj_label (int32), qus_type (int32), attention (f32), score_matrix (f32)
    const int*   obj_label = (const int*)d_in[0];
    const int*   qus_type  = (const int*)d_in[1];
    const float* attention = (const float*)d_in[2];
    const float* score     = (const float*)d_in[3];
    float* out = (float*)d_out;

    zero_cnt_kernel<<<1, 128, 0, 0>>>();
    build_kernel<<<(BATCH + 255) / 256, 256, 0, 0>>>(obj_label, qus_type, attention);
    fused_copy_scatter_kernel<<<NUM_QT * PAIR_NUM, 256, 0, 0>>>(score, out);
}

// round 11
// speedup vs baseline: 1.1191x; 1.1191x over previous
#include <cuda_runtime.h>
#include <cuda_bf16.h>
#include <stdint.h>

// Problem constants
#define NUM_QT   65
#define NUM_OT   151
#define PAIR_NUM 90
#define BATCH    8192
#define BOX      10
#define SLICE    (NUM_OT * NUM_OT)     // 22801 floats per (qt,p) slice
#define CAP      256                    // max batches per qt (mean 126, ~11 sigma headroom)
// out elements = 65*90*151*151 = 133,385,850 = 5850 * 22801 exactly

// Scratch (device globals — no allocation allowed)
__device__ int                g_cnt[NUM_QT];
// Layout [qt][pos][p]: build writes one batch's 90 entries contiguously (720B).
__device__ unsigned long long g_bucket[NUM_QT][CAP][PAIR_NUM];   // ~12 MB

__global__ void zero_cnt_kernel()
{
    int t = threadIdx.x;
    if (t < NUM_QT) g_cnt[t] = 0;
}

// One thread per batch: compute all 90 (cell, value) pairs, deposit contiguously.
__global__ void build_kernel(const int* __restrict__ obj_label,
                             const int* __restrict__ qus_type,
                             const float* __restrict__ attention)
{
    int b = blockIdx.x * blockDim.x + threadIdx.x;
    if (b >= BATCH) return;

    int qt = qus_type[b];
    int   lab[BOX];
    float att[BOX];
    #pragma unroll
    for (int k = 0; k < BOX; k++) {
        lab[k] = obj_label[b * BOX + k];
        att[k] = attention[b * BOX + k];
    }

    int pos = atomicAdd(&g_cnt[qt], 1);
    if (pos >= CAP) return;   // statistically impossible; guard anyway

    unsigned long long* dst = g_bucket[qt][pos];
    // Reference mapping: i = p/9, jj = p%9, j = jj + (jj>=i)
    //   ol1 = obj_label[b,j], ol2 = obj_label[b,i], a = att[b,j]*att[b,i]
    #pragma unroll
    for (int i = 0; i < BOX; i++) {
        #pragma unroll
        for (int jj = 0; jj < BOX - 1; jj++) {
            int j = jj + (jj >= i ? 1 : 0);
            int p = i * (BOX - 1) + jj;
            unsigned int cell = (unsigned int)(lab[j] * NUM_OT + lab[i]);
            float        v    = att[j] * att[i];
            dst[p] = ((unsigned long long)cell << 32)
                   | (unsigned long long)__float_as_uint(v);
        }
    }
}

// One block per (qt,p) slice:
//   1) prefetch this slice's bucket entries into smem (hidden under copy)
//   2) streaming copy (4-deep independent __ldcs/__stcs float4, like R3's copy)
//   3) __syncthreads, then atomicAdd the entries — lines just written, L2-hot.
__global__ __launch_bounds__(256)
void fused_copy_scatter_kernel(const float* __restrict__ src,
                               float* __restrict__ out)
{
    __shared__ int   s_cell[CAP];
    __shared__ float s_val[CAP];
    __shared__ int   s_n;

    const int s   = blockIdx.x;           // slice = qt*90 + p
    const int qt  = s / PAIR_NUM;
    const int p   = s - qt * PAIR_NUM;
    const int tid = threadIdx.x;

    // Prefetch bucket entries (issued first; latency overlaps the copy below)
    if (tid == 0) s_n = min(g_cnt[qt], CAP);
    int n_ub = CAP;                       // iterate to CAP; guard inside by s_n later
    for (int e = tid; e < n_ub; e += 256) {
        unsigned long long pk = g_bucket[qt][e][p];
        s_cell[e] = (int)(pk >> 32);
        s_val[e]  = __uint_as_float((unsigned int)pk);
    }

    const long long base = (long long)s * SLICE;
    const float* __restrict__ sp = src + base;
    float* __restrict__       dp = out + base;

    // 16B alignment prologue (src/dst share offset; base mod 4 varies per slice)
    int k = (int)((4 - (base & 3)) & 3);
    if (tid < k) __stcs(&dp[tid], __ldcs(&sp[tid]));

    const int nf4 = (SLICE - k) >> 2;
    const float4* __restrict__ sp4 = (const float4*)(sp + k);
    float4* __restrict__       dp4 = (float4*)(dp + k);

    // 4-deep independent load batches (R3 copy pattern)
    int c = tid;
    for (; c + 3 * 256 < nf4; c += 4 * 256) {
        float4 a = __ldcs(&sp4[c]);
        float4 b = __ldcs(&sp4[c + 256]);
        float4 d = __ldcs(&sp4[c + 512]);
        float4 e = __ldcs(&sp4[c + 768]);
        __stcs(&dp4[c],       a);
        __stcs(&dp4[c + 256], b);
        __stcs(&dp4[c + 512], d);
        __stcs(&dp4[c + 768], e);
    }
    for (; c < nf4; c += 256)
        __stcs(&dp4[c], __ldcs(&sp4[c]));

    const int done = k + (nf4 << 2);
    if (tid < SLICE - done)               // tail (<= 3 elems)
        __stcs(&dp[done + tid], __ldcs(&sp[done + tid]));

    __syncthreads();                      // stores visible block-wide; s_n/s_* ready

    const int n = s_n;
    for (int e = tid; e < n; e += 256)
        atomicAdd(&dp[s_cell[e]], s_val[e]);   // L2-hit: line stored moments ago
}

extern "C" void kernel_launch(void* const* d_in, const int* in_sizes, int n_in,
                              void* d_out, int out_size)
{
    // metadata order: obj_label (int32), qus_type (int32), attention (f32), score_matrix (f32)
    const int*   obj_label = (const int*)d_in[0];
    const int*   qus_type  = (const int*)d_in[1];
    const float* attention = (const float*)d_in[2];
    const float* score     = (const float*)d_in[3];
    float* out = (float*)d_out;

    zero_cnt_kernel<<<1, 128, 0, 0>>>();
    build_kernel<<<(BATCH + 255) / 256, 256, 0, 0>>>(obj_label, qus_type, attention);
    fused_copy_scatter_kernel<<<NUM_QT * PAIR_NUM, 256, 0, 0>>>(score, out);
}